// round 3
// baseline (speedup 1.0000x reference)
#include <cuda_runtime.h>
#include <math.h>

#define B_  4
#define T_  1024
#define C_  1024
#define H_  16
#define DH_ 64
#define M_  4096   /* B*T */

// ---------------- scratch (static __device__, no allocations) ----------------
__device__ float g_q[(size_t)M_ * C_];
__device__ float g_k[(size_t)M_ * C_];
__device__ float g_v[(size_t)M_ * C_];
__device__ float g_y[(size_t)M_ * C_];
__device__ unsigned char g_mask[(size_t)B_ * T_ * T_];
__device__ int g_mask_mode;   // 0 = u8/bool bytes, 1 = int32, 2 = float32

// ---------------- mask dtype probe ----------------
// Bool masks may be serialized as u8, int32 or float32 depending on the
// harness dtype mapping. Detect from byte patterns (deterministic: pure
// function of input bytes). i32 0/1 -> nonzero bytes only at pos%4==0.
// f32 1.0 -> bytes 0x80/0x3F (>1). u8 -> random 0/1 bytes everywhere.
__global__ void probe_mask_kernel(const unsigned char* __restrict__ m) {
    __shared__ int s_gt1, s_nzoff;
    if (threadIdx.x == 0) { s_gt1 = 0; s_nzoff = 0; }
    __syncthreads();
    int gt1 = 0, nz = 0;
    for (int i = threadIdx.x; i < 262144; i += blockDim.x) {
        unsigned char v = m[i];
        if (v > 1) gt1 = 1;
        else if (v && (i & 3)) nz = 1;
    }
    if (gt1) atomicOr(&s_gt1, 1);
    if (nz)  atomicOr(&s_nzoff, 1);
    __syncthreads();
    if (threadIdx.x == 0)
        g_mask_mode = s_gt1 ? 2 : (s_nzoff ? 0 : 1);
}

__global__ void normalize_mask_kernel(const void* __restrict__ m) {
    int i = blockIdx.x * blockDim.x + threadIdx.x;
    int mode = g_mask_mode;
    unsigned char r;
    if (mode == 1)      r = ((const int*)m)[i]   != 0;
    else if (mode == 2) r = ((const float*)m)[i] != 0.0f;
    else                r = ((const unsigned char*)m)[i] != 0;
    g_mask[i] = r;
}

// ---------------- NT GEMM: Out[m][n] = sum_k A[m][k]*W[n][k] ----------------
// M=4096, N=K=1024. 128x128x16 tile, 256 threads, 8x8 microtile (split 4+4).
__device__ __forceinline__ void gemm_body(const float* __restrict__ A,
                                          const float* __restrict__ W,
                                          float* __restrict__ Out,
                                          float scale,
                                          const float* __restrict__ bias) {
    __shared__ float As[16][128];
    __shared__ float Bs[16][128];
    const int tid = threadIdx.x;
    const int tn  = tid & 15;
    const int tm  = tid >> 4;
    const int m0  = blockIdx.y * 128;
    const int n0  = blockIdx.x * 128;
    const int lr  = tid >> 2;         // 0..63
    const int lc  = (tid & 3) << 2;   // 0,4,8,12

    float acc[8][8];
#pragma unroll
    for (int i = 0; i < 8; i++)
#pragma unroll
        for (int j = 0; j < 8; j++) acc[i][j] = 0.0f;

    const float* Aptr = A + (size_t)(m0 + lr) * C_ + lc;
    const float* Wptr = W + (size_t)(n0 + lr) * C_ + lc;

    for (int kt = 0; kt < C_; kt += 16) {
        float4 a0 = *(const float4*)(Aptr + kt);
        float4 a1 = *(const float4*)(Aptr + kt + 64 * C_);
        float4 b0 = *(const float4*)(Wptr + kt);
        float4 b1 = *(const float4*)(Wptr + kt + 64 * C_);
        __syncthreads();
        As[lc + 0][lr]      = a0.x; As[lc + 1][lr]      = a0.y;
        As[lc + 2][lr]      = a0.z; As[lc + 3][lr]      = a0.w;
        As[lc + 0][lr + 64] = a1.x; As[lc + 1][lr + 64] = a1.y;
        As[lc + 2][lr + 64] = a1.z; As[lc + 3][lr + 64] = a1.w;
        Bs[lc + 0][lr]      = b0.x; Bs[lc + 1][lr]      = b0.y;
        Bs[lc + 2][lr]      = b0.z; Bs[lc + 3][lr]      = b0.w;
        Bs[lc + 0][lr + 64] = b1.x; Bs[lc + 1][lr + 64] = b1.y;
        Bs[lc + 2][lr + 64] = b1.z; Bs[lc + 3][lr + 64] = b1.w;
        __syncthreads();
#pragma unroll
        for (int k = 0; k < 16; k++) {
            float a[8], b[8];
            *(float4*)&a[0] = *(const float4*)&As[k][tm * 4];
            *(float4*)&a[4] = *(const float4*)&As[k][64 + tm * 4];
            *(float4*)&b[0] = *(const float4*)&Bs[k][tn * 4];
            *(float4*)&b[4] = *(const float4*)&Bs[k][64 + tn * 4];
#pragma unroll
            for (int i = 0; i < 8; i++)
#pragma unroll
                for (int j = 0; j < 8; j++)
                    acc[i][j] += a[i] * b[j];
        }
    }
#pragma unroll
    for (int i = 0; i < 8; i++) {
        int row = m0 + ((i < 4) ? (tm * 4 + i) : (64 + tm * 4 + i - 4));
#pragma unroll
        for (int jq = 0; jq < 2; jq++) {
            int col = n0 + tn * 4 + jq * 64;
            float4 v;
            v.x = acc[i][jq * 4 + 0] * scale;
            v.y = acc[i][jq * 4 + 1] * scale;
            v.z = acc[i][jq * 4 + 2] * scale;
            v.w = acc[i][jq * 4 + 3] * scale;
            if (bias) {
                v.x += bias[col + 0]; v.y += bias[col + 1];
                v.z += bias[col + 2]; v.w += bias[col + 3];
            }
            *(float4*)(Out + (size_t)row * C_ + col) = v;
        }
    }
}

__global__ __launch_bounds__(256, 2) void qkv_gemm_kernel(
        const float* __restrict__ X,
        const float* __restrict__ Wq,
        const float* __restrict__ Wk,
        const float* __restrict__ Wv) {
    const float* W; float* O; float s;
    if (blockIdx.z == 0)      { W = Wq; O = g_q; s = 0.125f; }  // DH^-0.5
    else if (blockIdx.z == 1) { W = Wk; O = g_k; s = 1.0f; }
    else                      { W = Wv; O = g_v; s = 1.0f; }
    gemm_body(X, W, O, s, nullptr);
}

__global__ __launch_bounds__(256, 2) void proj_gemm_kernel(
        const float* __restrict__ Wo,
        const float* __restrict__ bo,
        float* __restrict__ out) {
    gemm_body(g_y, Wo, out, 1.0f, bo);
}

// ---------------- flash attention ----------------
// grid = (T/64, B*H). 256 threads. 64 q rows per block, 64 kv rows per iter.
__global__ __launch_bounds__(256) void attn_kernel() {
    __shared__ float Qs[64][64];   // Qs[d][i]   (transposed)
    __shared__ float KPs[64][64];  // K: [d][j] transposed, then P: [j][i]
    __shared__ float Vs[64][64];   // Vs[j][d]   (direct)

    const int tid = threadIdx.x;
    const int tx  = tid & 15;     // column group
    const int ty  = tid >> 4;     // row group
    const int bh  = blockIdx.y;
    const int b   = bh >> 4;      // H=16
    const int h   = bh & 15;
    const int q0  = blockIdx.x * 64;

    const int lr = tid >> 4;          // 0..15
    const int lc = (tid & 15) << 2;   // 0..60

    const float* qbase = g_q + (size_t)(b * T_ + q0) * C_ + h * DH_;
    const float* kbase = g_k + (size_t)(b * T_) * C_ + h * DH_;
    const float* vbase = g_v + (size_t)(b * T_) * C_ + h * DH_;
    const unsigned char* mbase = g_mask + (size_t)(b * T_ + q0) * T_;

#pragma unroll
    for (int rr = 0; rr < 4; rr++) {
        int r = lr + rr * 16;
        float4 v = *(const float4*)(qbase + (size_t)r * C_ + lc);
        Qs[lc + 0][r] = v.x; Qs[lc + 1][r] = v.y;
        Qs[lc + 2][r] = v.z; Qs[lc + 3][r] = v.w;
    }

    const float NEG = -3.402823466e38f;
    float m_i[4], l_i[4], o[4][4];
#pragma unroll
    for (int i = 0; i < 4; i++) {
        m_i[i] = NEG; l_i[i] = 0.0f;
#pragma unroll
        for (int j = 0; j < 4; j++) o[i][j] = 0.0f;
    }

    for (int jt = 0; jt < T_; jt += 64) {
        __syncthreads();   // prior-iter consumers of KPs/Vs done
#pragma unroll
        for (int rr = 0; rr < 4; rr++) {
            int r = lr + rr * 16;
            float4 kv = *(const float4*)(kbase + (size_t)(jt + r) * C_ + lc);
            KPs[lc + 0][r] = kv.x; KPs[lc + 1][r] = kv.y;
            KPs[lc + 2][r] = kv.z; KPs[lc + 3][r] = kv.w;
            float4 vv = *(const float4*)(vbase + (size_t)(jt + r) * C_ + lc);
            *(float4*)&Vs[r][lc] = vv;
        }
        __syncthreads();

        // S = Q K^T  (scale already folded into q)
        float s[4][4];
#pragma unroll
        for (int i = 0; i < 4; i++)
#pragma unroll
            for (int j = 0; j < 4; j++) s[i][j] = 0.0f;
#pragma unroll 16
        for (int d = 0; d < 64; d++) {
            float4 qv = *(const float4*)&Qs[d][ty * 4];
            float4 kv = *(const float4*)&KPs[d][tx * 4];
            float aa[4] = {qv.x, qv.y, qv.z, qv.w};
            float bb[4] = {kv.x, kv.y, kv.z, kv.w};
#pragma unroll
            for (int i = 0; i < 4; i++)
#pragma unroll
                for (int j = 0; j < 4; j++)
                    s[i][j] += aa[i] * bb[j];
        }

        // mask + online softmax (row groups = 16 consecutive lanes)
#pragma unroll
        for (int ii = 0; ii < 4; ii++) {
            int qg = 4 * ty + ii;
            const unsigned char* mp = mbase + (size_t)qg * T_ + jt + 4 * tx;
            float sv[4];
#pragma unroll
            for (int jj = 0; jj < 4; jj++)
                sv[jj] = mp[jj] ? s[ii][jj] : NEG;
            float mx = fmaxf(fmaxf(sv[0], sv[1]), fmaxf(sv[2], sv[3]));
#pragma unroll
            for (int off = 1; off < 16; off <<= 1)
                mx = fmaxf(mx, __shfl_xor_sync(0xffffffffu, mx, off));
            float mnew = fmaxf(m_i[ii], mx);
            float fac  = __expf(m_i[ii] - mnew);
            float rsum = 0.0f;
#pragma unroll
            for (int jj = 0; jj < 4; jj++) {
                float p = __expf(sv[jj] - mnew);
                s[ii][jj] = p;
                rsum += p;
            }
#pragma unroll
            for (int off = 1; off < 16; off <<= 1)
                rsum += __shfl_xor_sync(0xffffffffu, rsum, off);
            l_i[ii] = l_i[ii] * fac + rsum;
            m_i[ii] = mnew;
#pragma unroll
            for (int jj = 0; jj < 4; jj++) o[ii][jj] *= fac;
        }

        __syncthreads();   // all S-compute reads of KPs done
        // write P transposed into KPs: KPs[j][i]
#pragma unroll
        for (int ii = 0; ii < 4; ii++)
#pragma unroll
            for (int jj = 0; jj < 4; jj++)
                KPs[4 * tx + jj][4 * ty + ii] = s[ii][jj];
        __syncthreads();

        // O += P @ V
#pragma unroll 16
        for (int j = 0; j < 64; j++) {
            float4 pv = *(const float4*)&KPs[j][ty * 4];
            float4 vv = *(const float4*)&Vs[j][tx * 4];
            float pp[4] = {pv.x, pv.y, pv.z, pv.w};
            float vvv[4] = {vv.x, vv.y, vv.z, vv.w};
#pragma unroll
            for (int ii = 0; ii < 4; ii++)
#pragma unroll
                for (int jj = 0; jj < 4; jj++)
                    o[ii][jj] += pp[ii] * vvv[jj];
        }
    }

    float* ybase = g_y + (size_t)(b * T_ + q0) * C_ + h * DH_;
#pragma unroll
    for (int ii = 0; ii < 4; ii++) {
        float inv = 1.0f / l_i[ii];
        float4 v;
        v.x = o[ii][0] * inv; v.y = o[ii][1] * inv;
        v.z = o[ii][2] * inv; v.w = o[ii][3] * inv;
        *(float4*)(ybase + (size_t)(4 * ty + ii) * C_ + 4 * tx) = v;
    }
}

// ---------------- launch ----------------
extern "C" void kernel_launch(void* const* d_in, const int* in_sizes, int n_in,
                              void* d_out, int out_size) {
    const float* x    = (const float*)d_in[0];
    // d_in[1] = context (unused by reference forward)
    const void*  mask = d_in[2];
    const float* Wq   = (const float*)d_in[3];
    const float* Wk   = (const float*)d_in[4];
    const float* Wv   = (const float*)d_in[5];
    const float* Wo   = (const float*)d_in[6];
    const float* bo   = (const float*)d_in[7];
    float* out = (float*)d_out;

    probe_mask_kernel<<<1, 256>>>((const unsigned char*)mask);
    normalize_mask_kernel<<<(B_ * T_ * T_) / 1024, 1024>>>(mask);
    qkv_gemm_kernel<<<dim3(C_ / 128, M_ / 128, 3), 256>>>(x, Wq, Wk, Wv);
    attn_kernel<<<dim3(T_ / 64, B_ * H_), 256>>>();
    proj_gemm_kernel<<<dim3(C_ / 128, M_ / 128, 1), 256>>>(Wo, bo, out);
}

// round 6
// speedup vs baseline: 2.3305x; 2.3305x over previous
#include <cuda_runtime.h>
#include <math.h>
#include <stdint.h>

#define B_  4
#define T_  1024
#define C_  1024
#define H_  16
#define DH_ 64
#define M_  4096   /* B*T */

// ---------------- scratch (static __device__, no allocations) ----------------
__device__ float g_q[(size_t)M_ * C_];
__device__ float g_k[(size_t)M_ * C_];
__device__ float g_v[(size_t)M_ * C_];
__device__ float g_y[(size_t)M_ * C_];
__device__ float g_xt[(size_t)M_ * C_];          // tf32-rounded x
__device__ float g_wt[4][(size_t)C_ * C_];       // tf32-rounded Wq,Wk,Wv,Wo
__device__ unsigned char g_mask[(size_t)B_ * T_ * T_];
__device__ int g_mask_mode;   // 0 = u8 bytes, 1 = int32, 2 = float32

#define NEGF (-3.402823466e38f)

// ---------------- small helpers ----------------
// cvt.rna.tf32.f32 requires a .b32 destination (ptxas rejects an f32 reg).
__device__ __forceinline__ float to_tf32(float x) {
    uint32_t r;
    asm("cvt.rna.tf32.f32 %0, %1;" : "=r"(r) : "f"(x));
    return __uint_as_float(r);
}

__device__ __forceinline__ void mma8(float* c, const float* a, const float* b) {
    asm volatile(
        "mma.sync.aligned.m16n8k8.row.col.f32.tf32.tf32.f32 "
        "{%0,%1,%2,%3}, {%4,%5,%6,%7}, {%8,%9}, {%0,%1,%2,%3};"
        : "+f"(c[0]), "+f"(c[1]), "+f"(c[2]), "+f"(c[3])
        : "r"(__float_as_uint(a[0])), "r"(__float_as_uint(a[1])),
          "r"(__float_as_uint(a[2])), "r"(__float_as_uint(a[3])),
          "r"(__float_as_uint(b[0])), "r"(__float_as_uint(b[1])));
}

__device__ __forceinline__ void cp16(void* smem, const void* gmem) {
    uint32_t s = (uint32_t)__cvta_generic_to_shared(smem);
    asm volatile("cp.async.cg.shared.global [%0], [%1], 16;" :: "r"(s), "l"(gmem));
}
__device__ __forceinline__ void cp_commit() { asm volatile("cp.async.commit_group;"); }
template <int N>
__device__ __forceinline__ void cp_wait() { asm volatile("cp.async.wait_group %0;" :: "n"(N)); }

// ---------------- mask dtype probe + normalize ----------------
__global__ void probe_mask_kernel(const unsigned char* __restrict__ m) {
    __shared__ int s_gt1, s_nzoff;
    if (threadIdx.x == 0) { s_gt1 = 0; s_nzoff = 0; }
    __syncthreads();
    int gt1 = 0, nz = 0;
    for (int i = threadIdx.x; i < 262144; i += blockDim.x) {
        unsigned char v = m[i];
        if (v > 1) gt1 = 1;
        else if (v && (i & 3)) nz = 1;
    }
    if (gt1) atomicOr(&s_gt1, 1);
    if (nz)  atomicOr(&s_nzoff, 1);
    __syncthreads();
    if (threadIdx.x == 0)
        g_mask_mode = s_gt1 ? 2 : (s_nzoff ? 0 : 1);
}

__global__ void normalize_mask_kernel(const void* __restrict__ m) {
    int i = blockIdx.x * blockDim.x + threadIdx.x;
    int mode = g_mask_mode;
    unsigned char r;
    if (mode == 1)      r = ((const int*)m)[i]   != 0;
    else if (mode == 2) r = ((const float*)m)[i] != 0.0f;
    else                r = ((const unsigned char*)m)[i] != 0;
    g_mask[i] = r;
}

// ---------------- pre-round GEMM inputs to tf32 ----------------
__global__ void round_inputs_kernel(const float* __restrict__ x,
                                    const float* __restrict__ wq,
                                    const float* __restrict__ wk,
                                    const float* __restrict__ wv,
                                    const float* __restrict__ wo) {
    int i = blockIdx.x * blockDim.x + threadIdx.x;   // 0 .. 8M-1
    if (i < M_ * C_) {
        g_xt[i] = to_tf32(x[i]);
    } else {
        int j = i - M_ * C_;              // 0 .. 4M-1
        int w = j >> 20;                  // C_*C_ = 2^20
        int r = j & (C_ * C_ - 1);
        const float* src = (w == 0) ? wq : (w == 1) ? wk : (w == 2) ? wv : wo;
        g_wt[w][r] = to_tf32(src[r]);
    }
}

// ---------------- tf32 mma NT GEMM: Out[m][n] = sum_k A[m][k]*W[n][k] ----------------
// 128x128 CTA tile, 128 threads (4 warps in 2x2), warp tile 64x64, k-tile 16, cp.async dbuf.
#define GS 20   /* SMEM row stride (floats): 20 mod 32 -> conflict-free frag loads */

__device__ __forceinline__ void gemm128(const float* __restrict__ A,
                                        const float* __restrict__ W,
                                        float* __restrict__ Out,
                                        float scale,
                                        const float* __restrict__ bias,
                                        int do_round) {
    __shared__ float As[2][128 * GS];
    __shared__ float Bs[2][128 * GS];
    const int tid  = threadIdx.x;
    const int warp = tid >> 5, lane = tid & 31;
    const int g = lane >> 2, tg = lane & 3;
    const int wm = warp >> 1, wn = warp & 1;
    const int m0 = blockIdx.y * 128, n0 = blockIdx.x * 128;

    float acc[4][8][4];
#pragma unroll
    for (int mf = 0; mf < 4; mf++)
#pragma unroll
        for (int nf = 0; nf < 8; nf++)
#pragma unroll
            for (int q = 0; q < 4; q++) acc[mf][nf][q] = 0.0f;

#pragma unroll
    for (int i = 0; i < 4; i++) {       // prologue: tile 0
        int chunk = i * 128 + tid, row = chunk >> 2, c4 = (chunk & 3) * 4;
        cp16(&As[0][row * GS + c4], A + (size_t)(m0 + row) * C_ + c4);
        cp16(&Bs[0][row * GS + c4], W + (size_t)(n0 + row) * C_ + c4);
    }
    cp_commit();

    for (int kt = 0; kt < 64; kt++) {
        int buf = kt & 1;
        if (kt < 63) {
#pragma unroll
            for (int i = 0; i < 4; i++) {
                int chunk = i * 128 + tid, row = chunk >> 2, c4 = (chunk & 3) * 4;
                cp16(&As[buf ^ 1][row * GS + c4],
                     A + (size_t)(m0 + row) * C_ + (kt + 1) * 16 + c4);
                cp16(&Bs[buf ^ 1][row * GS + c4],
                     W + (size_t)(n0 + row) * C_ + (kt + 1) * 16 + c4);
            }
            cp_commit();
            cp_wait<1>();
        } else {
            cp_wait<0>();
        }
        __syncthreads();
        const float* as = As[buf];
        const float* bs = Bs[buf];
#pragma unroll
        for (int ks = 0; ks < 2; ks++) {
            const int k0 = ks * 8;
            float a[4][4], b[8][2];
#pragma unroll
            for (int mf = 0; mf < 4; mf++) {
                int r = wm * 64 + mf * 16 + g;
                a[mf][0] = as[r * GS + k0 + tg];
                a[mf][1] = as[(r + 8) * GS + k0 + tg];
                a[mf][2] = as[r * GS + k0 + tg + 4];
                a[mf][3] = as[(r + 8) * GS + k0 + tg + 4];
            }
#pragma unroll
            for (int nf = 0; nf < 8; nf++) {
                int c = wn * 64 + nf * 8 + g;
                b[nf][0] = bs[c * GS + k0 + tg];
                b[nf][1] = bs[c * GS + k0 + tg + 4];
            }
#pragma unroll
            for (int mf = 0; mf < 4; mf++)
#pragma unroll
                for (int nf = 0; nf < 8; nf++)
                    mma8(acc[mf][nf], a[mf], b[nf]);
        }
        __syncthreads();
    }

#pragma unroll
    for (int mf = 0; mf < 4; mf++) {
        int r0 = m0 + wm * 64 + mf * 16 + g;
#pragma unroll
        for (int nf = 0; nf < 8; nf++) {
            int c = n0 + wn * 64 + nf * 8 + 2 * tg;
            float v0 = acc[mf][nf][0] * scale, v1 = acc[mf][nf][1] * scale;
            float v2 = acc[mf][nf][2] * scale, v3 = acc[mf][nf][3] * scale;
            if (bias) { v0 += bias[c]; v1 += bias[c + 1]; v2 += bias[c]; v3 += bias[c + 1]; }
            if (do_round) { v0 = to_tf32(v0); v1 = to_tf32(v1); v2 = to_tf32(v2); v3 = to_tf32(v3); }
            *(float2*)(Out + (size_t)r0 * C_ + c)       = make_float2(v0, v1);
            *(float2*)(Out + (size_t)(r0 + 8) * C_ + c) = make_float2(v2, v3);
        }
    }
}

__global__ __launch_bounds__(128) void qkv_mma_kernel() {
    if (blockIdx.z == 0)      gemm128(g_xt, g_wt[0], g_q, 0.125f, nullptr, 1);
    else if (blockIdx.z == 1) gemm128(g_xt, g_wt[1], g_k, 1.0f,  nullptr, 1);
    else                      gemm128(g_xt, g_wt[2], g_v, 1.0f,  nullptr, 1);
}

__global__ __launch_bounds__(128) void proj_mma_kernel(const float* __restrict__ bo,
                                                       float* __restrict__ out) {
    gemm128(g_y, g_wt[3], out, 1.0f, bo, 0);
}

// ---------------- tf32 mma flash attention ----------------
// grid (T/64, B*H), 128 threads. Warp w owns rows [16w,16w+16) x all 64 cols.
// Q fragments in registers; KP buffer holds K then P; V stored transposed.
__global__ __launch_bounds__(128) void attn_mma_kernel() {
    __shared__ float KP[64 * 68];
    __shared__ float Vt[64 * 68];
    const int tid  = threadIdx.x;
    const int warp = tid >> 5, lane = tid & 31;
    const int g = lane >> 2, tg = lane & 3;
    const int i0 = warp * 16;
    const int bh = blockIdx.y, b = bh >> 4, h = bh & 15;
    const int q0 = blockIdx.x * 64;

    const float* qg = g_q + (size_t)(b * T_ + q0) * C_ + h * DH_;
    const float* kg = g_k + (size_t)(b * T_) * C_ + h * DH_;
    const float* vg = g_v + (size_t)(b * T_) * C_ + h * DH_;

    // stage Q tile -> KP -> registers
#pragma unroll
    for (int i = 0; i < 8; i++) {
        int chunk = i * 128 + tid, row = chunk >> 4, c4 = (chunk & 15) * 4;
        float4 v = *(const float4*)(qg + (size_t)row * C_ + c4);
        KP[row * 68 + c4 + 0] = v.x; KP[row * 68 + c4 + 1] = v.y;
        KP[row * 68 + c4 + 2] = v.z; KP[row * 68 + c4 + 3] = v.w;
    }
    __syncthreads();
    float qa[8][4];
#pragma unroll
    for (int kk = 0; kk < 8; kk++) {
        qa[kk][0] = KP[(i0 + g) * 68 + kk * 8 + tg];
        qa[kk][1] = KP[(i0 + g + 8) * 68 + kk * 8 + tg];
        qa[kk][2] = KP[(i0 + g) * 68 + kk * 8 + tg + 4];
        qa[kk][3] = KP[(i0 + g + 8) * 68 + kk * 8 + tg + 4];
    }

    float o[8][4];
#pragma unroll
    for (int f = 0; f < 8; f++)
#pragma unroll
        for (int q = 0; q < 4; q++) o[f][q] = 0.0f;
    float mi0 = NEGF, mi1 = NEGF, li0 = 0.0f, li1 = 0.0f;

    const unsigned char* mrow0 = g_mask + (size_t)(b * T_ + q0 + i0 + g) * T_;
    const unsigned char* mrow1 = mrow0 + (size_t)8 * T_;

    for (int jt = 0; jt < T_; jt += 64) {
        __syncthreads();   // prior consumers of KP/Vt (and Q staging) done
#pragma unroll
        for (int i = 0; i < 8; i++) {
            int chunk = i * 128 + tid, row = chunk >> 4, c4 = (chunk & 15) * 4;
            float4 kv = *(const float4*)(kg + (size_t)(jt + row) * C_ + c4);
            KP[row * 68 + c4 + 0] = kv.x; KP[row * 68 + c4 + 1] = kv.y;
            KP[row * 68 + c4 + 2] = kv.z; KP[row * 68 + c4 + 3] = kv.w;
            float4 vv = *(const float4*)(vg + (size_t)(jt + row) * C_ + c4);
            Vt[(c4 + 0) * 68 + row] = vv.x; Vt[(c4 + 1) * 68 + row] = vv.y;
            Vt[(c4 + 2) * 68 + row] = vv.z; Vt[(c4 + 3) * 68 + row] = vv.w;
        }
        __syncthreads();

        // S = Q K^T (64x64 per block; 16x64 per warp)
        float s[8][4];
#pragma unroll
        for (int f = 0; f < 8; f++)
#pragma unroll
            for (int q = 0; q < 4; q++) s[f][q] = 0.0f;
#pragma unroll
        for (int kk = 0; kk < 8; kk++) {
#pragma unroll
            for (int f = 0; f < 8; f++) {
                float bb[2];
                bb[0] = KP[(f * 8 + g) * 68 + kk * 8 + tg];
                bb[1] = KP[(f * 8 + g) * 68 + kk * 8 + tg + 4];
                mma8(s[f], qa[kk], bb);
            }
        }

        // mask + row max
        float mx0 = NEGF, mx1 = NEGF;
#pragma unroll
        for (int f = 0; f < 8; f++) {
            int c = jt + f * 8 + 2 * tg;
            if (!mrow0[c])     s[f][0] = NEGF;
            if (!mrow0[c + 1]) s[f][1] = NEGF;
            if (!mrow1[c])     s[f][2] = NEGF;
            if (!mrow1[c + 1]) s[f][3] = NEGF;
            mx0 = fmaxf(mx0, fmaxf(s[f][0], s[f][1]));
            mx1 = fmaxf(mx1, fmaxf(s[f][2], s[f][3]));
        }
        mx0 = fmaxf(mx0, __shfl_xor_sync(0xffffffffu, mx0, 1));
        mx0 = fmaxf(mx0, __shfl_xor_sync(0xffffffffu, mx0, 2));
        mx1 = fmaxf(mx1, __shfl_xor_sync(0xffffffffu, mx1, 1));
        mx1 = fmaxf(mx1, __shfl_xor_sync(0xffffffffu, mx1, 2));

        float mn0 = fmaxf(mi0, mx0), mn1 = fmaxf(mi1, mx1);
        float f0 = __expf(mi0 - mn0), f1 = __expf(mi1 - mn1);

        __syncthreads();   // every warp finished reading KP as K
        float rs0 = 0.0f, rs1 = 0.0f;
#pragma unroll
        for (int f = 0; f < 8; f++) {
            float p0 = __expf(s[f][0] - mn0);
            float p1 = __expf(s[f][1] - mn0);
            float p2 = __expf(s[f][2] - mn1);
            float p3 = __expf(s[f][3] - mn1);
            rs0 += p0 + p1; rs1 += p2 + p3;
            int c = f * 8 + 2 * tg;
            KP[(i0 + g) * 68 + c]         = to_tf32(p0);
            KP[(i0 + g) * 68 + c + 1]     = to_tf32(p1);
            KP[(i0 + g + 8) * 68 + c]     = to_tf32(p2);
            KP[(i0 + g + 8) * 68 + c + 1] = to_tf32(p3);
        }
        rs0 += __shfl_xor_sync(0xffffffffu, rs0, 1);
        rs0 += __shfl_xor_sync(0xffffffffu, rs0, 2);
        rs1 += __shfl_xor_sync(0xffffffffu, rs1, 1);
        rs1 += __shfl_xor_sync(0xffffffffu, rs1, 2);
        li0 = li0 * f0 + rs0; li1 = li1 * f1 + rs1;
        mi0 = mn0; mi1 = mn1;
#pragma unroll
        for (int f = 0; f < 8; f++) {
            o[f][0] *= f0; o[f][1] *= f0; o[f][2] *= f1; o[f][3] *= f1;
        }
        __syncwarp();      // P rows for this warp visible (only own warp reads them)

        // O += P V  (A frags = own 16 P rows, B = Vt)
#pragma unroll
        for (int kk = 0; kk < 8; kk++) {
            float pa[4];
            pa[0] = KP[(i0 + g) * 68 + kk * 8 + tg];
            pa[1] = KP[(i0 + g + 8) * 68 + kk * 8 + tg];
            pa[2] = KP[(i0 + g) * 68 + kk * 8 + tg + 4];
            pa[3] = KP[(i0 + g + 8) * 68 + kk * 8 + tg + 4];
#pragma unroll
            for (int f = 0; f < 8; f++) {
                float bb[2];
                bb[0] = Vt[(f * 8 + g) * 68 + kk * 8 + tg];
                bb[1] = Vt[(f * 8 + g) * 68 + kk * 8 + tg + 4];
                mma8(o[f], pa, bb);
            }
        }
    }

    float* yg = g_y + (size_t)(b * T_ + q0) * C_ + h * DH_;
    float inv0 = 1.0f / li0, inv1 = 1.0f / li1;
#pragma unroll
    for (int f = 0; f < 8; f++) {
        int c = f * 8 + 2 * tg;
        *(float2*)(yg + (size_t)(i0 + g) * C_ + c) =
            make_float2(to_tf32(o[f][0] * inv0), to_tf32(o[f][1] * inv0));
        *(float2*)(yg + (size_t)(i0 + g + 8) * C_ + c) =
            make_float2(to_tf32(o[f][2] * inv1), to_tf32(o[f][3] * inv1));
    }
}

// ---------------- launch ----------------
extern "C" void kernel_launch(void* const* d_in, const int* in_sizes, int n_in,
                              void* d_out, int out_size) {
    const float* x    = (const float*)d_in[0];
    // d_in[1] = context (unused by reference forward)
    const void*  mask = d_in[2];
    const float* Wq   = (const float*)d_in[3];
    const float* Wk   = (const float*)d_in[4];
    const float* Wv   = (const float*)d_in[5];
    const float* Wo   = (const float*)d_in[6];
    const float* bo   = (const float*)d_in[7];
    float* out = (float*)d_out;

    probe_mask_kernel<<<1, 256>>>((const unsigned char*)mask);
    normalize_mask_kernel<<<(B_ * T_ * T_) / 1024, 1024>>>(mask);
    round_inputs_kernel<<<(2 * M_ * C_) / 256, 256>>>(x, Wq, Wk, Wv, Wo);
    qkv_mma_kernel<<<dim3(C_ / 128, M_ / 128, 3), 128>>>();
    attn_mma_kernel<<<dim3(T_ / 64, B_ * H_), 128>>>();
    proj_mma_kernel<<<dim3(C_ / 128, M_ / 128, 1), 128>>>(bo, out);
}